// round 13
// baseline (speedup 1.0000x reference)
#include <cuda_runtime.h>
#include <math.h>
#include <stdint.h>

// Problem constants
#define EDIM 384
#define GDIM 256
#define HNUM 6
#define DHH  64
#define OUTD 256
#define HE   (HNUM*EDIM)   // 2304
#define UNIT 128
#define SLOTS 8            // MAX_N 1024 / UNIT
#define NUNITS (GDIM*SLOTS)

// ---------------- device scratch ----------------
__device__ __align__(16) float g_wk[HNUM*EDIM];
__device__ __align__(16) float g_Wc[OUTD*EDIM];      // Wp @ Wo
__device__ __align__(16) float g_cb[OUTD];           // Wp.bo + bp
__device__            int   g_off[GDIM + 1];
__device__ __align__(16) float g_accx[GDIM*HE];      // attn-weighted x sums (atomic)
__device__ __align__(16) float g_pooled[GDIM*EDIM];  // pooled incl. bv
__device__ __align__(16) float g_sexp[(size_t)NUNITS*UNIT*8];  // exp scores [u][n][8] ~8.4MB
__device__ __align__(16) float g_usum[NUNITS*HNUM];  // per-unit exp sums

// ---------------- helpers ----------------
__device__ __forceinline__ float warp_sum(float v) {
#pragma unroll
    for (int s = 16; s > 0; s >>= 1) v += __shfl_xor_sync(0xffffffffu, v, s);
    return v;
}

// ---------------- prep: wkq (blocks 0..5) + scan (6) + cb (7..28) ----------
__global__ void __launch_bounds__(EDIM)
prep_kernel(const float* __restrict__ Wq, const float* __restrict__ query,
            const float* __restrict__ bq, const float* __restrict__ Wk,
            const int* __restrict__ sizes, const float* __restrict__ Wp,
            const float* __restrict__ bo, const float* __restrict__ bp) {
    int b = blockIdx.x;
    int tid = threadIdx.x;
    int warp = tid >> 5;
    int lane = tid & 31;
    if (b < HNUM) {
        int h = b;
        __shared__ float qs[DHH];
        for (int d = warp; d < DHH; d += 12) {
            int row = h * DHH + d;
            float s = 0.f;
            for (int j = lane; j < EDIM; j += 32) s += Wq[(size_t)row * EDIM + j] * query[j];
            s = warp_sum(s);
            if (lane == 0) qs[d] = (s + bq[row]) * 0.125f;
        }
        __syncthreads();
        float s = 0.f;
#pragma unroll 8
        for (int d = 0; d < DHH; d++)
            s += qs[d] * Wk[(size_t)(h * DHH + d) * EDIM + tid];
        g_wk[h * EDIM + tid] = s;
    } else if (b == HNUM) {
        __shared__ int s[GDIM];
        if (tid < GDIM) s[tid] = sizes[tid];
        __syncthreads();
        for (int d = 1; d < GDIM; d <<= 1) {
            int add = (tid < GDIM && tid >= d) ? s[tid - d] : 0;
            __syncthreads();
            if (tid < GDIM) s[tid] += add;
            __syncthreads();
        }
        if (tid < GDIM) {
            g_off[tid] = s[tid] - sizes[tid];
            if (tid == GDIM - 1) g_off[GDIM] = s[tid];
        }
    } else {
        int gw = (b - HNUM - 1) * 12 + warp;
        if (gw < OUTD) {
            float s = 0.f;
            for (int j = lane; j < EDIM; j += 32) s += Wp[(size_t)gw * EDIM + j] * bo[j];
            s = warp_sum(s);
            if (lane == 0) g_cb[gw] = s + bp[gw];
        }
    }
}

// ---------------- 64x32-tiled fp32 GEMM, 4x4 microtile, 128 threads ------
template <bool TB, bool BIAS>
__global__ void __launch_bounds__(128)
gemm_s(const float* __restrict__ A, int lda,
       const float* __restrict__ B, int ldb,
       float* __restrict__ C, int ldc,
       const float* __restrict__ bias,
       int M, int N, int K,
       int zA, int zB, int zC, int zBias) {
    A += (size_t)blockIdx.z * zA;
    B += (size_t)blockIdx.z * zB;
    C += (size_t)blockIdx.z * zC;
    if (BIAS) bias += (size_t)blockIdx.z * zBias;

    __shared__ float As[32][68];
    __shared__ float Bs[32][36];
    int tid = threadIdx.x;
    int bm = blockIdx.y * 64, bn = blockIdx.x * 32;
    int tx = tid & 7, ty = tid >> 3;

    float acc[4][4];
#pragma unroll
    for (int i = 0; i < 4; i++)
#pragma unroll
        for (int j = 0; j < 4; j++) acc[i][j] = 0.f;

    for (int k0 = 0; k0 < K; k0 += 32) {
        {
            int kk = tid & 31, mb = tid >> 5;
#pragma unroll
            for (int i = 0; i < 16; i++) {
                int mm = mb + i * 4;
                As[kk][mm] = A[(size_t)(bm + mm) * lda + k0 + kk];
            }
        }
        if (TB) {
            int kk = tid & 31, nb = tid >> 5;
#pragma unroll
            for (int i = 0; i < 8; i++) {
                int nn = nb + i * 4;
                Bs[kk][nn] = B[(size_t)(bn + nn) * ldb + k0 + kk];
            }
        } else {
            int nn = tid & 31, kb = tid >> 5;
#pragma unroll
            for (int i = 0; i < 8; i++) {
                int k2 = kb + i * 4;
                Bs[k2][nn] = B[(size_t)(k0 + k2) * ldb + bn + nn];
            }
        }
        __syncthreads();
#pragma unroll
        for (int kk = 0; kk < 32; kk++) {
            float4 a = *(const float4*)&As[kk][ty * 4];
            float4 bb = *(const float4*)&Bs[kk][tx * 4];
            acc[0][0] = fmaf(a.x, bb.x, acc[0][0]); acc[0][1] = fmaf(a.x, bb.y, acc[0][1]);
            acc[0][2] = fmaf(a.x, bb.z, acc[0][2]); acc[0][3] = fmaf(a.x, bb.w, acc[0][3]);
            acc[1][0] = fmaf(a.y, bb.x, acc[1][0]); acc[1][1] = fmaf(a.y, bb.y, acc[1][1]);
            acc[1][2] = fmaf(a.y, bb.z, acc[1][2]); acc[1][3] = fmaf(a.y, bb.w, acc[1][3]);
            acc[2][0] = fmaf(a.z, bb.x, acc[2][0]); acc[2][1] = fmaf(a.z, bb.y, acc[2][1]);
            acc[2][2] = fmaf(a.z, bb.z, acc[2][2]); acc[2][3] = fmaf(a.z, bb.w, acc[2][3]);
            acc[3][0] = fmaf(a.w, bb.x, acc[3][0]); acc[3][1] = fmaf(a.w, bb.y, acc[3][1]);
            acc[3][2] = fmaf(a.w, bb.z, acc[3][2]); acc[3][3] = fmaf(a.w, bb.w, acc[3][3]);
        }
        __syncthreads();
    }
    float4 bv4 = make_float4(0.f, 0.f, 0.f, 0.f);
    if (BIAS) bv4 = *(const float4*)&bias[bn + tx * 4];
#pragma unroll
    for (int i = 0; i < 4; i++) {
        int gm = bm + ty * 4 + i;
        float4 o = make_float4(acc[i][0] + bv4.x, acc[i][1] + bv4.y,
                               acc[i][2] + bv4.z, acc[i][3] + bv4.w);
        *(float4*)&C[(size_t)gm * ldc + bn + tx * 4] = o;
    }
}

// ---------------- kernel A: scores -> exp, per-unit sums ----------------
// block = unit. 8 warps, fully independent: warp (hgrp=w>>2, ph=w&3) handles
// heads hgrp*3..+2 for nodes n ≡ ph (mod 4). No barriers until the tiny
// final sum reduce. Max-free softmax (scores ~ N(0,1); exp cannot overflow).
__global__ void __launch_bounds__(256)
scores_kernel(const float* __restrict__ x, const int* __restrict__ sizes) {
    __shared__ float s_rs[8][4];
    int u = blockIdx.x;
    int g = u >> 3;
    int slot = u & (SLOTS - 1);
    int size = sizes[g];
    int ustart = slot * UNIT;
    if (ustart >= size) return;
    int ucnt = min(UNIT, size - ustart);
    int off = g_off[g] + ustart;

    int tid = threadIdx.x;
    int warp = tid >> 5;
    int lane = tid & 31;
    int hgrp = warp >> 2;     // heads hgrp*3 .. hgrp*3+2
    int ph = warp & 3;        // node phase

    // per-lane score weights for 3 heads (36 regs)
    float4 w0[3], w1[3], w2[3];
#pragma unroll
    for (int j = 0; j < 3; j++) {
        w0[j] = *(const float4*)(&g_wk[(hgrp * 3 + 0) * EDIM + j * 128 + lane * 4]);
        w1[j] = *(const float4*)(&g_wk[(hgrp * 3 + 1) * EDIM + j * 128 + lane * 4]);
        w2[j] = *(const float4*)(&g_wk[(hgrp * 3 + 2) * EDIM + j * 128 + lane * 4]);
    }

    float rs = 0.f;
#pragma unroll 2
    for (int n = ph; n < ucnt; n += 4) {
        const float4* row = (const float4*)(x + (size_t)(off + n) * EDIM);
        float4 x0 = row[lane];
        float4 x1 = row[lane + 32];
        float4 x2 = row[lane + 64];
        float p0, p1, p2;
        p0 = w0[0].x * x0.x;            p1 = w1[0].x * x0.x;            p2 = w2[0].x * x0.x;
        p0 = fmaf(w0[0].y, x0.y, p0);   p1 = fmaf(w1[0].y, x0.y, p1);   p2 = fmaf(w2[0].y, x0.y, p2);
        p0 = fmaf(w0[0].z, x0.z, p0);   p1 = fmaf(w1[0].z, x0.z, p1);   p2 = fmaf(w2[0].z, x0.z, p2);
        p0 = fmaf(w0[0].w, x0.w, p0);   p1 = fmaf(w1[0].w, x0.w, p1);   p2 = fmaf(w2[0].w, x0.w, p2);
        p0 = fmaf(w0[1].x, x1.x, p0);   p1 = fmaf(w1[1].x, x1.x, p1);   p2 = fmaf(w2[1].x, x1.x, p2);
        p0 = fmaf(w0[1].y, x1.y, p0);   p1 = fmaf(w1[1].y, x1.y, p1);   p2 = fmaf(w2[1].y, x1.y, p2);
        p0 = fmaf(w0[1].z, x1.z, p0);   p1 = fmaf(w1[1].z, x1.z, p1);   p2 = fmaf(w2[1].z, x1.z, p2);
        p0 = fmaf(w0[1].w, x1.w, p0);   p1 = fmaf(w1[1].w, x1.w, p1);   p2 = fmaf(w2[1].w, x1.w, p2);
        p0 = fmaf(w0[2].x, x2.x, p0);   p1 = fmaf(w1[2].x, x2.x, p1);   p2 = fmaf(w2[2].x, x2.x, p2);
        p0 = fmaf(w0[2].y, x2.y, p0);   p1 = fmaf(w1[2].y, x2.y, p1);   p2 = fmaf(w2[2].y, x2.y, p2);
        p0 = fmaf(w0[2].z, x2.z, p0);   p1 = fmaf(w1[2].z, x2.z, p1);   p2 = fmaf(w2[2].z, x2.z, p2);
        p0 = fmaf(w0[2].w, x2.w, p0);   p1 = fmaf(w1[2].w, x2.w, p1);   p2 = fmaf(w2[2].w, x2.w, p2);
#pragma unroll
        for (int sft = 16; sft > 0; sft >>= 1) {
            p0 += __shfl_xor_sync(0xffffffffu, p0, sft);
            p1 += __shfl_xor_sync(0xffffffffu, p1, sft);
            p2 += __shfl_xor_sync(0xffffffffu, p2, sft);
        }
        float v = (lane == 0) ? p0 : ((lane == 1) ? p1 : p2);
        float ev = __expf(v);
        if (lane < 3) {
            g_sexp[((size_t)u * UNIT + n) * 8 + hgrp * 3 + lane] = ev;
            rs += ev;
        }
    }
    if (lane < 3) s_rs[warp][lane] = rs;
    __syncthreads();
    if (tid < HNUM) {
        int hg = tid / 3, hl = tid % 3;
        float s = s_rs[hg * 4 + 0][hl] + s_rs[hg * 4 + 1][hl]
                + s_rs[hg * 4 + 2][hl] + s_rs[hg * 4 + 3][hl];
        g_usum[u * HNUM + tid] = s;
    }
}

// ---------------- kernel B: weighted accumulate (atomic into g_accx) -------
// block = unit, 384 threads thread-per-column. Stage exp scores (4 KB), then
// barrier-free n-loop, 4-deep LDG unroll, 6 atomicAdds at the end.
__global__ void __launch_bounds__(384)
accum_kernel(const float* __restrict__ x, const int* __restrict__ sizes) {
    __shared__ float4 s_sc[UNIT * 2];   // [n][8] floats = [n*2] float4
    int u = blockIdx.x;
    int g = u >> 3;
    int slot = u & (SLOTS - 1);
    int size = sizes[g];
    int ustart = slot * UNIT;
    if (ustart >= size) return;
    int ucnt = min(UNIT, size - ustart);
    int off = g_off[g] + ustart;
    int tid = threadIdx.x;

    const float4* gs = (const float4*)&g_sexp[(size_t)u * UNIT * 8];
    for (int i = tid; i < ucnt * 2; i += 384) s_sc[i] = gs[i];
    __syncthreads();

    const float* px = x + (size_t)off * EDIM + tid;
    float acc[HNUM];
#pragma unroll
    for (int h = 0; h < HNUM; h++) acc[h] = 0.f;

    int n = 0;
    for (; n + 4 <= ucnt; n += 4) {
        float xv0 = px[(size_t)(n + 0) * EDIM];
        float xv1 = px[(size_t)(n + 1) * EDIM];
        float xv2 = px[(size_t)(n + 2) * EDIM];
        float xv3 = px[(size_t)(n + 3) * EDIM];
#pragma unroll
        for (int k = 0; k < 4; k++) {
            float xv = (k == 0) ? xv0 : (k == 1) ? xv1 : (k == 2) ? xv2 : xv3;
            float4 a4 = s_sc[(n + k) * 2];
            float4 a2 = s_sc[(n + k) * 2 + 1];
            acc[0] = fmaf(a4.x, xv, acc[0]);
            acc[1] = fmaf(a4.y, xv, acc[1]);
            acc[2] = fmaf(a4.z, xv, acc[2]);
            acc[3] = fmaf(a4.w, xv, acc[3]);
            acc[4] = fmaf(a2.x, xv, acc[4]);
            acc[5] = fmaf(a2.y, xv, acc[5]);
        }
    }
    for (; n < ucnt; n++) {
        float xv = px[(size_t)n * EDIM];
        float4 a4 = s_sc[n * 2];
        float4 a2 = s_sc[n * 2 + 1];
        acc[0] = fmaf(a4.x, xv, acc[0]);
        acc[1] = fmaf(a4.y, xv, acc[1]);
        acc[2] = fmaf(a4.z, xv, acc[2]);
        acc[3] = fmaf(a4.w, xv, acc[3]);
        acc[4] = fmaf(a2.x, xv, acc[4]);
        acc[5] = fmaf(a2.y, xv, acc[5]);
    }

    float* dst = &g_accx[(size_t)g * HE + tid];
#pragma unroll
    for (int h = 0; h < HNUM; h++)
        atomicAdd(dst + h * EDIM, acc[h]);
}

// ---------------- normalize accx by per-group exp sums ----------------
__global__ void __launch_bounds__(EDIM)
norm_kernel(const int* __restrict__ sizes) {
    __shared__ float s_inv[HNUM];
    int g = blockIdx.x;
    int tid = threadIdx.x;
    int nslots = (sizes[g] + UNIT - 1) / UNIT;
    if (tid < HNUM) {
        float d = 0.f;
        for (int s = 0; s < nslots; s++) d += g_usum[(g * SLOTS + s) * HNUM + tid];
        s_inv[tid] = 1.f / d;
    }
    __syncthreads();
#pragma unroll
    for (int h = 0; h < HNUM; h++)
        g_accx[(size_t)g * HE + h * EDIM + tid] *= s_inv[h];
}

// ---------------- launch ----------------
extern "C" void kernel_launch(void* const* d_in, const int* in_sizes, int n_in,
                              void* d_out, int out_size) {
    const float* node_feat = (const float*)d_in[0];
    const int*   sizes     = (const int*)d_in[1];
    const float* query     = (const float*)d_in[2];
    const float* Wq        = (const float*)d_in[3];
    const float* bq        = (const float*)d_in[4];
    const float* Wk        = (const float*)d_in[5];
    /* bk = d_in[6] cancels in softmax */
    const float* Wv        = (const float*)d_in[7];
    const float* bv        = (const float*)d_in[8];
    const float* Wo        = (const float*)d_in[9];
    const float* bo        = (const float*)d_in[10];
    const float* Wp        = (const float*)d_in[11];
    const float* bp        = (const float*)d_in[12];
    float* out = (float*)d_out;

    float *pWc, *pcb, *paccx, *ppooled;
    cudaGetSymbolAddress((void**)&pWc, g_Wc);
    cudaGetSymbolAddress((void**)&pcb, g_cb);
    cudaGetSymbolAddress((void**)&paccx, g_accx);
    cudaGetSymbolAddress((void**)&ppooled, g_pooled);

    cudaMemsetAsync(paccx, 0, (size_t)GDIM * HE * sizeof(float));

    // prep: wkq + scan + cb in one launch
    prep_kernel<<<HNUM + 1 + 22, EDIM>>>(Wq, query, bq, Wk, sizes, Wp, bo, bp);

    // Wc = Wp @ Wo   [256,384]
    gemm_s<false, false><<<dim3(EDIM / 32, OUTD / 64, 1), 128>>>(
        Wp, EDIM, Wo, EDIM, pWc, EDIM, nullptr, OUTD, EDIM, EDIM, 0, 0, 0, 0);

    // attention: scores -> accumulate -> normalize
    scores_kernel<<<NUNITS, 256>>>(node_feat, sizes);
    accum_kernel<<<NUNITS, 384>>>(node_feat, sizes);
    norm_kernel<<<GDIM, EDIM>>>(sizes);

    // pooled[g, h*64+d] = bv + Wv_h . accx_h   (batched over h)
    gemm_s<true, true><<<dim3(DHH / 32, GDIM / 64, HNUM), 128>>>(
        paccx, HE, Wv, EDIM, ppooled, EDIM, bv,
        GDIM, DHH, EDIM, /*zA=*/EDIM, /*zB=*/DHH * EDIM, /*zC=*/DHH, /*zBias=*/DHH);

    // out = pooled @ Wc^T + cb   [256,256]
    gemm_s<true, true><<<dim3(OUTD / 32, GDIM / 64, 1), 128>>>(
        ppooled, EDIM, pWc, EDIM, out, OUTD, pcb,
        GDIM, OUTD, EDIM, 0, 0, 0, 0);
}